// round 2
// baseline (speedup 1.0000x reference)
#include <cuda_runtime.h>
#include <math.h>

#define BB  32
#define INCD 2048
#define SS  512

// ---------------- scratch (static device globals; no allocs) ----------------
__device__ float g_bufA[(long)BB * SS * SS];   // G, then E/attn (in place)
__device__ float g_bufB[(long)BB * SS * SS];   // M1
__device__ float g_part[16 * BB * SS];         // colsum partials
__device__ float g_s [BB * SS];                // s = X^T 1
__device__ float g_kk[BB * SS];                // Wk s
__device__ float g_kq[BB * SS];                // Wq s
__device__ float g_w [BB * SS];                // w = attn^T Wout
__device__ float g_u [BB * SS];                // u = Wv^T w
__device__ float g_cc[BB];                     // w.bv + bout

// ---------------- column sums: s[b,c] = sum_i X[b,i,c] ----------------------
__global__ void colsum_part_kernel(const float* __restrict__ x) {
    int slab = blockIdx.x;          // 0..15, 128 rows each
    int b    = blockIdx.y;
    int c    = threadIdx.x;         // 0..511
    const float* p = x + ((long)b * INCD + slab * 128) * SS + c;
    float acc = 0.f;
    #pragma unroll 8
    for (int i = 0; i < 128; i++) acc += p[(long)i * SS];
    g_part[(slab * BB + b) * SS + c] = acc;
}

__global__ void colsum_reduce_kernel() {
    int b = blockIdx.x, c = threadIdx.x;
    float acc = 0.f;
    #pragma unroll
    for (int slab = 0; slab < 16; slab++) acc += g_part[(slab * BB + b) * SS + c];
    g_s[b * SS + c] = acc;
}

// ---------------- kk = Wk s, kq = Wq s ---------------------------------------
__global__ void kkq_kernel(const float* __restrict__ Wk, const float* __restrict__ Wq) {
    int b = blockIdx.x;
    int which = blockIdx.y;         // 0 -> kk (Wk), 1 -> kq (Wq)
    int row = threadIdx.x;
    __shared__ float ss[SS];
    ss[row] = g_s[b * SS + row];
    __syncthreads();
    const float* W = which ? Wq : Wk;
    const float* wr = W + (long)row * SS;
    float acc = 0.f;
    #pragma unroll 8
    for (int c = 0; c < SS; c++) acc += wr[c] * ss[c];
    if (which) g_kq[b * SS + row] = acc;
    else       g_kk[b * SS + row] = acc;
}

// ---------------- generic 64x64x16 fp32 GEMM ---------------------------------
// C[m,n] = sum_k opA(A)[m,k] * opB(B)[k,n]   (+ optional rank-1 epilogue)
// TA: opA = A^T with A[k*lda+m];  !TA: A[m*lda+k]
// TB: opB[k,n] = B[n*ldb+k];      !TB: B[k*ldb+n]
template <bool TA, bool TB, bool EPI>
__global__ void __launch_bounds__(256)
gemm64_kernel(const float* __restrict__ A, long sA, int lda,
              const float* __restrict__ B, long sB, int ldb,
              float* __restrict__ C, long sC, int K,
              const float* __restrict__ e_rm,   // kk   (batch-strided, per-m)
              const float* __restrict__ e_rn,   // kq   (batch-strided, per-n)
              const float* __restrict__ e_bm,   // bk   (per-m)
              const float* __restrict__ e_bn,   // bq   (per-n)
              float e_scale)                    // INC
{
    __shared__ float As[16][68];
    __shared__ float Bs[16][68];

    int tid = threadIdx.x;
    int tx = tid & 15, ty = tid >> 4;
    int m0 = blockIdx.y * 64, n0 = blockIdx.x * 64;
    int b  = blockIdx.z;

    A += (long)b * sA;
    B += (long)b * sB;
    C += (long)b * sC;

    float acc[4][4];
    #pragma unroll
    for (int i = 0; i < 4; i++)
        #pragma unroll
        for (int j = 0; j < 4; j++) acc[i][j] = 0.f;

    for (int k0 = 0; k0 < K; k0 += 16) {
        // ---- load A tile -> As[k][m]
        if (TA) {
            int r = tid >> 4, c = (tid & 15) * 4;
            float4 v = *(const float4*)(A + (long)(k0 + r) * lda + m0 + c);
            *(float4*)&As[r][c] = v;
        } else {
            int m = tid >> 2, kb = (tid & 3) * 4;
            float4 v = *(const float4*)(A + (long)(m0 + m) * lda + k0 + kb);
            As[kb + 0][m] = v.x; As[kb + 1][m] = v.y;
            As[kb + 2][m] = v.z; As[kb + 3][m] = v.w;
        }
        // ---- load B tile -> Bs[k][n]
        if (!TB) {
            int r = tid >> 4, c = (tid & 15) * 4;
            float4 v = *(const float4*)(B + (long)(k0 + r) * ldb + n0 + c);
            *(float4*)&Bs[r][c] = v;
        } else {
            int n = tid >> 2, kb = (tid & 3) * 4;
            float4 v = *(const float4*)(B + (long)(n0 + n) * ldb + k0 + kb);
            Bs[kb + 0][n] = v.x; Bs[kb + 1][n] = v.y;
            Bs[kb + 2][n] = v.z; Bs[kb + 3][n] = v.w;
        }
        __syncthreads();

        #pragma unroll
        for (int k = 0; k < 16; k++) {
            float4 a4 = *(const float4*)&As[k][ty * 4];
            float4 b4 = *(const float4*)&Bs[k][tx * 4];
            float av[4] = {a4.x, a4.y, a4.z, a4.w};
            float bv[4] = {b4.x, b4.y, b4.z, b4.w};
            #pragma unroll
            for (int i = 0; i < 4; i++)
                #pragma unroll
                for (int j = 0; j < 4; j++)
                    acc[i][j] += av[i] * bv[j];
        }
        __syncthreads();
    }

    const float* erm = EPI ? (e_rm + (long)b * SS) : nullptr;
    const float* ern = EPI ? (e_rn + (long)b * SS) : nullptr;

    #pragma unroll
    for (int i = 0; i < 4; i++) {
        int m = m0 + ty * 4 + i;
        float km = 0.f, bm = 0.f;
        if (EPI) { km = erm[m]; bm = e_bm[m]; }
        float4 o;
        float vals[4];
        #pragma unroll
        for (int j = 0; j < 4; j++) {
            int n = n0 + tx * 4 + j;
            float v = acc[i][j];
            if (EPI) v += km * e_bn[n] + bm * (ern[n] + e_scale * e_bn[n]);
            vals[j] = v;
        }
        o.x = vals[0]; o.y = vals[1]; o.z = vals[2]; o.w = vals[3];
        *(float4*)(C + (long)m * SS + n0 + tx * 4) = o;
    }
}

// ---------------- softmax over rows (in place on g_bufA) ---------------------
__global__ void softmax_kernel() {
    long row = (long)blockIdx.x * SS;
    float* p = g_bufA + row;
    int tid = threadIdx.x;             // 256 threads, 2 elems each
    float e0 = p[tid], e1 = p[tid + 256];

    __shared__ float red[256];
    red[tid] = fmaxf(e0, e1);
    __syncthreads();
    for (int s = 128; s > 0; s >>= 1) {
        if (tid < s) red[tid] = fmaxf(red[tid], red[tid + s]);
        __syncthreads();
    }
    float mx = red[0];
    __syncthreads();

    e0 = expf(e0 - mx);
    e1 = expf(e1 - mx);
    red[tid] = e0 + e1;
    __syncthreads();
    for (int s = 128; s > 0; s >>= 1) {
        if (tid < s) red[tid] += red[tid + s];
        __syncthreads();
    }
    float inv = 1.f / red[0];
    p[tid]       = e0 * inv;
    p[tid + 256] = e1 * inv;
}

// ---------------- w[b,t] = sum_s Wout[s] * attn[b,s,t] -----------------------
__global__ void w_kernel(const float* __restrict__ Wout) {
    int b = blockIdx.x, t = threadIdx.x;
    __shared__ float wo[SS];
    wo[t] = Wout[t];
    __syncthreads();
    const float* a = g_bufA + (long)b * SS * SS + t;
    float acc = 0.f;
    #pragma unroll 8
    for (int s = 0; s < SS; s++) acc += wo[s] * a[(long)s * SS];
    g_w[b * SS + t] = acc;
}

// ---------------- u[b,c] = sum_t w[b,t] Wv[t,c];  cc[b] = w.bv + bout --------
__global__ void u_kernel(const float* __restrict__ Wv,
                         const float* __restrict__ bv,
                         const float* __restrict__ bout) {
    int b = blockIdx.x, c = threadIdx.x;
    __shared__ float ws[SS];
    __shared__ float red[SS];
    ws[c] = g_w[b * SS + c];
    __syncthreads();
    float acc = 0.f;
    #pragma unroll 8
    for (int t = 0; t < SS; t++) acc += ws[t] * Wv[(long)t * SS + c];
    g_u[b * SS + c] = acc;
    red[c] = ws[c] * bv[c];
    __syncthreads();
    for (int s = 256; s > 0; s >>= 1) {
        if (c < s) red[c] += red[c + s];
        __syncthreads();
    }
    if (c == 0) g_cc[b] = red[0] + bout[0];
}

// ---------------- out[b,i] = X[b,i,:].u[b] + cc[b] ---------------------------
__global__ void out_kernel(const float* __restrict__ x, float* __restrict__ out) {
    int b  = blockIdx.y;
    int i0 = blockIdx.x * 8;
    int tid = threadIdx.x;
    __shared__ float us[SS];
    us[tid]       = g_u[b * SS + tid];
    us[tid + 256] = g_u[b * SS + tid + 256];
    __syncthreads();

    int warp = tid >> 5, lane = tid & 31;
    int i = i0 + warp;
    const float* xr = x + ((long)b * INCD + i) * SS;
    float acc = 0.f;
    #pragma unroll
    for (int s = lane; s < SS; s += 32) acc += xr[s] * us[s];
    #pragma unroll
    for (int o = 16; o > 0; o >>= 1) acc += __shfl_xor_sync(0xffffffffu, acc, o);
    if (lane == 0) out[(long)b * INCD + i] = acc + g_cc[b];
}

// ---------------- launch -----------------------------------------------------
extern "C" void kernel_launch(void* const* d_in, const int* in_sizes, int n_in,
                              void* d_out, int out_size) {
    const float* x    = (const float*)d_in[0];
    const float* Wq   = (const float*)d_in[1];
    const float* bq   = (const float*)d_in[2];
    const float* Wk   = (const float*)d_in[3];
    const float* bk   = (const float*)d_in[4];
    const float* Wv   = (const float*)d_in[5];
    const float* bv   = (const float*)d_in[6];
    const float* Wout = (const float*)d_in[7];
    const float* bout = (const float*)d_in[8];
    float* out = (float*)d_out;

    void *pA, *pB, *pkk, *pkq;
    cudaGetSymbolAddress(&pA,  g_bufA);
    cudaGetSymbolAddress(&pB,  g_bufB);
    cudaGetSymbolAddress(&pkk, g_kk);
    cudaGetSymbolAddress(&pkq, g_kq);
    float* bufA = (float*)pA;
    float* bufB = (float*)pB;
    float* kk   = (float*)pkk;
    float* kq   = (float*)pkq;

    const long sBatch = (long)SS * SS;
    const long sX     = (long)INCD * SS;

    // 1) column sums
    colsum_part_kernel<<<dim3(16, BB), SS>>>(x);
    colsum_reduce_kernel<<<BB, SS>>>();

    // 2) kk = Wk s, kq = Wq s
    kkq_kernel<<<dim3(BB, 2), SS>>>(Wk, Wq);

    // 3) G = X^T X  (K = 2048)
    gemm64_kernel<true, false, false><<<dim3(8, 8, BB), 256>>>(
        x, sX, SS, x, sX, SS, bufA, sBatch, INCD,
        nullptr, nullptr, nullptr, nullptr, 0.f);

    // 4) M1 = G Wq^T
    gemm64_kernel<false, true, false><<<dim3(8, 8, BB), 256>>>(
        bufA, sBatch, SS, Wq, 0, SS, bufB, sBatch, SS,
        nullptr, nullptr, nullptr, nullptr, 0.f);

    // 5) E = Wk M1 + kk bq^T + bk kq^T + INC bk bq^T   (into bufA)
    gemm64_kernel<false, false, true><<<dim3(8, 8, BB), 256>>>(
        Wk, 0, SS, bufB, sBatch, SS, bufA, sBatch, SS,
        kk, kq, bk, bq, (float)INCD);

    // 6) softmax rows of E (in place)
    softmax_kernel<<<BB * SS, 256>>>();

    // 7) w = attn^T Wout
    w_kernel<<<BB, SS>>>(Wout);

    // 8) u = Wv^T w, cc = w.bv + bout
    u_kernel<<<BB, SS>>>(Wv, bv, bout);

    // 9) out = X u + cc
    out_kernel<<<dim3(INCD / 8, BB), 256>>>(x, out);
}

// round 3
// speedup vs baseline: 1.3345x; 1.3345x over previous
#include <cuda_runtime.h>
#include <math.h>

#define BB   32
#define INCD 2048
#define SS   512

// ---------------- scratch (static device globals; no allocs) ----------------
__device__ float g_bufA[(long)BB * SS * SS];   // G, then E (in place)
__device__ float g_bufB[(long)BB * SS * SS];   // M2 = G Wk^T
__device__ float g_part[32 * BB * SS];         // colsum + w partials
__device__ float g_s [BB * SS];                // s = X^T 1
__device__ float g_kk[BB * SS];                // Wk s
__device__ float g_kq[BB * SS];                // Wq s
__device__ float g_w [BB * SS];                // w = attn^T Wout
__device__ float g_u [BB * SS];                // u = Wv^T w
__device__ float g_cc[BB];                     // w.bv + bout

// ---------------- column sums: s[b,c] = sum_i X[b,i,c] ----------------------
__global__ void colsum_part_kernel(const float* __restrict__ x) {
    int slab = blockIdx.x;          // 0..15, 128 rows each
    int b    = blockIdx.y;
    int c    = threadIdx.x;         // 0..511
    const float* p = x + ((long)b * INCD + slab * 128) * SS + c;
    float acc = 0.f;
    #pragma unroll 8
    for (int i = 0; i < 128; i++) acc += p[i * SS];
    g_part[(slab * BB + b) * SS + c] = acc;
}

__global__ void colsum_reduce_kernel() {
    int b = blockIdx.x, c = threadIdx.x;
    float acc = 0.f;
    #pragma unroll
    for (int slab = 0; slab < 16; slab++) acc += g_part[(slab * BB + b) * SS + c];
    g_s[b * SS + c] = acc;
}

// ---------------- kk = Wk s, kq = Wq s ---------------------------------------
__global__ void kkq_kernel(const float* __restrict__ Wk, const float* __restrict__ Wq) {
    int b = blockIdx.x;
    int which = blockIdx.y;
    int row = threadIdx.x;
    __shared__ float ss[SS];
    ss[row] = g_s[b * SS + row];
    __syncthreads();
    const float* W = which ? Wq : Wk;
    const float* wr = W + row * SS;
    float acc = 0.f;
    #pragma unroll 8
    for (int c = 0; c < SS; c++) acc += wr[c] * ss[c];
    if (which) g_kq[b * SS + row] = acc;
    else       g_kk[b * SS + row] = acc;
}

// =============================================================================
// GRAM: G = X^T X, symmetric. 128x128x8 tiles, 8x8 microtile, double buffered.
// Only upper-triangular tile pairs computed; off-diagonal mirrored.
// =============================================================================
__global__ void __launch_bounds__(256, 2)
gram_kernel(const float* __restrict__ x, float* __restrict__ C) {
    const int TI[10] = {0,0,0,0,1,1,1,2,2,3};
    const int TJ[10] = {0,1,2,3,1,2,3,2,3,3};
    int pair = blockIdx.x;
    int b    = blockIdx.y;
    int m0 = TI[pair] * 128, n0 = TJ[pair] * 128;

    const float* A = x + (long)b * INCD * SS;
    C += (long)b * SS * SS;

    __shared__ float As[2][8][132];
    __shared__ float Bs[2][8][132];

    int tid = threadIdx.x;
    int tx = tid & 15, ty = tid >> 4;
    int lr = tid >> 5, lc = (tid & 31) * 4;   // tile-load coords

    // prefetch chunk 0
    float4 pa = *(const float4*)(A + lr * SS + m0 + lc);
    float4 pb = *(const float4*)(A + lr * SS + n0 + lc);
    *(float4*)&As[0][lr][lc] = pa;
    *(float4*)&Bs[0][lr][lc] = pb;
    __syncthreads();

    float acc[8][8];
    #pragma unroll
    for (int i = 0; i < 8; i++)
        #pragma unroll
        for (int j = 0; j < 8; j++) acc[i][j] = 0.f;

    const int NC = INCD / 8;   // 256
    int st = 0;
    for (int c = 0; c < NC; c++) {
        if (c + 1 < NC) {
            const float* Arow = A + ((c + 1) * 8 + lr) * SS;
            pa = *(const float4*)(Arow + m0 + lc);
            pb = *(const float4*)(Arow + n0 + lc);
        }
        #pragma unroll
        for (int k = 0; k < 8; k++) {
            float4 a0 = *(const float4*)&As[st][k][ty * 4];
            float4 a1 = *(const float4*)&As[st][k][ty * 4 + 64];
            float4 b0 = *(const float4*)&Bs[st][k][tx * 4];
            float4 b1 = *(const float4*)&Bs[st][k][tx * 4 + 64];
            float av[8] = {a0.x,a0.y,a0.z,a0.w,a1.x,a1.y,a1.z,a1.w};
            float bv[8] = {b0.x,b0.y,b0.z,b0.w,b1.x,b1.y,b1.z,b1.w};
            #pragma unroll
            for (int i = 0; i < 8; i++)
                #pragma unroll
                for (int j = 0; j < 8; j++)
                    acc[i][j] += av[i] * bv[j];
        }
        if (c + 1 < NC) {
            *(float4*)&As[st ^ 1][lr][lc] = pa;
            *(float4*)&Bs[st ^ 1][lr][lc] = pb;
        }
        __syncthreads();
        st ^= 1;
    }

    // write normal block
    #pragma unroll
    for (int i = 0; i < 8; i++) {
        int m = m0 + ty * 4 + (i & 3) + (i >> 2) * 64;
        float4 v0 = {acc[i][0], acc[i][1], acc[i][2], acc[i][3]};
        float4 v1 = {acc[i][4], acc[i][5], acc[i][6], acc[i][7]};
        *(float4*)(C + m * SS + n0 + tx * 4)      = v0;
        *(float4*)(C + m * SS + n0 + tx * 4 + 64) = v1;
    }
    // mirror block (transpose) for off-diagonal tiles
    if (m0 != n0) {
        #pragma unroll
        for (int j = 0; j < 8; j++) {
            int n = n0 + tx * 4 + (j & 3) + (j >> 2) * 64;
            #pragma unroll
            for (int i = 0; i < 8; i++) {
                int m = m0 + ty * 4 + (i & 3) + (i >> 2) * 64;
                C[n * SS + m] = acc[i][j];
            }
        }
    }
}

// =============================================================================
// GEMM: C[m,n] = sum_k A[k*512+m] * B[n*512+k]   (A read "TA-direct", B TB)
//   M2 = G Wk^T   : A=G (symmetric => G[k][m]=G[m][k]), B=Wk
//   E  = M2^T Wq^T: A=M2,                              B=Wq  (+rank-1 epi)
// 128x128x8, 8x8 microtile, double buffered.
// =============================================================================
template <bool EPI>
__global__ void __launch_bounds__(256, 2)
gemm128_kernel(const float* __restrict__ A, long sA,
               const float* __restrict__ B,
               float* __restrict__ C, long sC,
               const float* __restrict__ e_rm,   // kk  [b][m]
               const float* __restrict__ e_rn,   // kq  [b][n]
               const float* __restrict__ e_bm,   // bk  [m]
               const float* __restrict__ e_bn,   // bq  [n]
               float e_scale)
{
    int m0 = blockIdx.y * 128, n0 = blockIdx.x * 128;
    int b  = blockIdx.z;
    A += (long)b * sA;
    C += (long)b * sC;

    __shared__ float As[2][8][132];
    __shared__ float Bs[2][8][132];

    int tid = threadIdx.x;
    int tx = tid & 15, ty = tid >> 4;
    int lr = tid >> 5, lc = (tid & 31) * 4;       // A-load coords
    int bn = tid >> 1, bk4 = (tid & 1) * 4;       // B-load coords

    // prefetch chunk 0
    float4 pa = *(const float4*)(A + lr * SS + m0 + lc);
    float4 pb = *(const float4*)(B + (n0 + bn) * SS + bk4);
    *(float4*)&As[0][lr][lc] = pa;
    Bs[0][bk4 + 0][bn] = pb.x; Bs[0][bk4 + 1][bn] = pb.y;
    Bs[0][bk4 + 2][bn] = pb.z; Bs[0][bk4 + 3][bn] = pb.w;
    __syncthreads();

    float acc[8][8];
    #pragma unroll
    for (int i = 0; i < 8; i++)
        #pragma unroll
        for (int j = 0; j < 8; j++) acc[i][j] = 0.f;

    const int NC = SS / 8;   // 64
    int st = 0;
    for (int c = 0; c < NC; c++) {
        if (c + 1 < NC) {
            int k0 = (c + 1) * 8;
            pa = *(const float4*)(A + (k0 + lr) * SS + m0 + lc);
            pb = *(const float4*)(B + (n0 + bn) * SS + k0 + bk4);
        }
        #pragma unroll
        for (int k = 0; k < 8; k++) {
            float4 a0 = *(const float4*)&As[st][k][ty * 4];
            float4 a1 = *(const float4*)&As[st][k][ty * 4 + 64];
            float4 b0 = *(const float4*)&Bs[st][k][tx * 4];
            float4 b1 = *(const float4*)&Bs[st][k][tx * 4 + 64];
            float av[8] = {a0.x,a0.y,a0.z,a0.w,a1.x,a1.y,a1.z,a1.w};
            float bv[8] = {b0.x,b0.y,b0.z,b0.w,b1.x,b1.y,b1.z,b1.w};
            #pragma unroll
            for (int i = 0; i < 8; i++)
                #pragma unroll
                for (int j = 0; j < 8; j++)
                    acc[i][j] += av[i] * bv[j];
        }
        if (c + 1 < NC) {
            *(float4*)&As[st ^ 1][lr][lc] = pa;
            Bs[st ^ 1][bk4 + 0][bn] = pb.x; Bs[st ^ 1][bk4 + 1][bn] = pb.y;
            Bs[st ^ 1][bk4 + 2][bn] = pb.z; Bs[st ^ 1][bk4 + 3][bn] = pb.w;
        }
        __syncthreads();
        st ^= 1;
    }

    const float* erm = EPI ? (e_rm + b * SS) : nullptr;
    const float* ern = EPI ? (e_rn + b * SS) : nullptr;

    #pragma unroll
    for (int i = 0; i < 8; i++) {
        int m = m0 + ty * 4 + (i & 3) + (i >> 2) * 64;
        float km = 0.f, bm = 0.f;
        if (EPI) { km = erm[m]; bm = e_bm[m]; }
        float vals[8];
        #pragma unroll
        for (int j = 0; j < 8; j++) {
            int n = n0 + tx * 4 + (j & 3) + (j >> 2) * 64;
            float v = acc[i][j];
            if (EPI) v += km * e_bn[n] + bm * (ern[n] + e_scale * e_bn[n]);
            vals[j] = v;
        }
        float4 v0 = {vals[0], vals[1], vals[2], vals[3]};
        float4 v1 = {vals[4], vals[5], vals[6], vals[7]};
        *(float4*)(C + m * SS + n0 + tx * 4)      = v0;
        *(float4*)(C + m * SS + n0 + tx * 4 + 64) = v1;
    }
}

// =============================================================================
// Fused softmax + partial w: block = (b, chunk of 16 rows).
// wpart[t] = sum_{s in chunk} Wout[s] * softmax(E[b,s,:])[t]  -> g_part
// =============================================================================
__global__ void softmax_w_kernel(const float* __restrict__ Wout) {
    int chunk = blockIdx.x;     // 0..31
    int b     = blockIdx.y;
    int tid   = threadIdx.x;    // 256

    __shared__ float red[256];
    __shared__ float wpart[SS];

    wpart[tid] = 0.f;
    wpart[tid + 256] = 0.f;
    __syncthreads();

    const float* Eb = g_bufA + (long)b * SS * SS;

    for (int r = 0; r < 16; r++) {
        int s = chunk * 16 + r;
        const float* row = Eb + s * SS;
        float e0 = row[tid], e1 = row[tid + 256];

        red[tid] = fmaxf(e0, e1);
        __syncthreads();
        for (int st = 128; st > 0; st >>= 1) {
            if (tid < st) red[tid] = fmaxf(red[tid], red[tid + st]);
            __syncthreads();
        }
        float mx = red[0];
        __syncthreads();

        e0 = expf(e0 - mx);
        e1 = expf(e1 - mx);
        red[tid] = e0 + e1;
        __syncthreads();
        for (int st = 128; st > 0; st >>= 1) {
            if (tid < st) red[tid] += red[tid + st];
            __syncthreads();
        }
        float scale = Wout[s] / red[0];
        wpart[tid]       += e0 * scale;
        wpart[tid + 256] += e1 * scale;
        __syncthreads();
    }

    float* dst = g_part + (chunk * BB + b) * SS;
    dst[tid]       = wpart[tid];
    dst[tid + 256] = wpart[tid + 256];
}

__global__ void w_reduce_kernel() {
    int b = blockIdx.x, t = threadIdx.x;
    float acc = 0.f;
    #pragma unroll
    for (int chunk = 0; chunk < 32; chunk++) acc += g_part[(chunk * BB + b) * SS + t];
    g_w[b * SS + t] = acc;
}

// ---------------- u[b,c] = sum_t w[b,t] Wv[t,c];  cc[b] = w.bv + bout --------
__global__ void u_kernel(const float* __restrict__ Wv,
                         const float* __restrict__ bv,
                         const float* __restrict__ bout) {
    int b = blockIdx.x, c = threadIdx.x;
    __shared__ float ws[SS];
    __shared__ float red[SS];
    ws[c] = g_w[b * SS + c];
    __syncthreads();
    float acc = 0.f;
    #pragma unroll 8
    for (int t = 0; t < SS; t++) acc += ws[t] * Wv[t * SS + c];
    g_u[b * SS + c] = acc;
    red[c] = ws[c] * bv[c];
    __syncthreads();
    for (int s = 256; s > 0; s >>= 1) {
        if (c < s) red[c] += red[c + s];
        __syncthreads();
    }
    if (c == 0) g_cc[b] = red[0] + bout[0];
}

// ---------------- out[b,i] = X[b,i,:].u[b] + cc[b] ---------------------------
__global__ void out_kernel(const float* __restrict__ x, float* __restrict__ out) {
    int b  = blockIdx.y;
    int i0 = blockIdx.x * 8;
    int tid = threadIdx.x;
    __shared__ float us[SS];
    us[tid]       = g_u[b * SS + tid];
    us[tid + 256] = g_u[b * SS + tid + 256];
    __syncthreads();

    int warp = tid >> 5, lane = tid & 31;
    int i = i0 + warp;
    const float* xr = x + ((long)b * INCD + i) * SS;
    float acc = 0.f;
    #pragma unroll
    for (int s = lane; s < SS; s += 32) acc += xr[s] * us[s];
    #pragma unroll
    for (int o = 16; o > 0; o >>= 1) acc += __shfl_xor_sync(0xffffffffu, acc, o);
    if (lane == 0) out[(long)b * INCD + i] = acc + g_cc[b];
}

// ---------------- launch -----------------------------------------------------
extern "C" void kernel_launch(void* const* d_in, const int* in_sizes, int n_in,
                              void* d_out, int out_size) {
    const float* x    = (const float*)d_in[0];
    const float* Wq   = (const float*)d_in[1];
    const float* bq   = (const float*)d_in[2];
    const float* Wk   = (const float*)d_in[3];
    const float* bk   = (const float*)d_in[4];
    const float* Wv   = (const float*)d_in[5];
    const float* bv   = (const float*)d_in[6];
    const float* Wout = (const float*)d_in[7];
    const float* bout = (const float*)d_in[8];
    float* out = (float*)d_out;

    void *pA, *pB, *pkk, *pkq;
    cudaGetSymbolAddress(&pA,  g_bufA);
    cudaGetSymbolAddress(&pB,  g_bufB);
    cudaGetSymbolAddress(&pkk, g_kk);
    cudaGetSymbolAddress(&pkq, g_kq);
    float* bufA = (float*)pA;
    float* bufB = (float*)pB;
    float* kk   = (float*)pkk;
    float* kq   = (float*)pkq;

    const long sBatch = (long)SS * SS;

    // 1) column sums -> s, then kk = Wk s, kq = Wq s
    colsum_part_kernel<<<dim3(16, BB), SS>>>(x);
    colsum_reduce_kernel<<<BB, SS>>>();
    kkq_kernel<<<dim3(BB, 2), SS>>>(Wk, Wq);

    // 2) G = X^T X (symmetric, upper tiles + mirror) -> bufA
    gram_kernel<<<dim3(10, BB), 256>>>(x, bufA);

    // 3) M2 = G Wk^T -> bufB
    gemm128_kernel<false><<<dim3(4, 4, BB), 256>>>(
        bufA, sBatch, Wk, bufB, sBatch,
        nullptr, nullptr, nullptr, nullptr, 0.f);

    // 4) E = M2^T Wq^T (= Wk G Wq^T) + rank-1 -> bufA
    gemm128_kernel<true><<<dim3(4, 4, BB), 256>>>(
        bufB, sBatch, Wq, bufA, sBatch,
        kk, kq, bk, bq, (float)INCD);

    // 5) fused softmax + w partials, then reduce
    softmax_w_kernel<<<dim3(32, BB), 256>>>(Wout);
    w_reduce_kernel<<<BB, SS>>>();

    // 6) u = Wv^T w, cc = w.bv + bout
    u_kernel<<<BB, SS>>>(Wv, bv, bout);

    // 7) out = X u + cc
    out_kernel<<<dim3(INCD / 8, BB), 256>>>(x, out);
}

// round 11
// speedup vs baseline: 1.6114x; 1.2075x over previous
#include <cuda_runtime.h>
#include <cuda_bf16.h>
#include <math.h>
#include <stdint.h>

#define BB   32
#define INCD 2048
#define SS   512

// ---------------- scratch (static device globals; no allocs) ----------------
__device__ float g_bufA[(long)BB * SS * SS];   // G, then E (in place)
__device__ float g_bufB[(long)BB * SS * SS];   // M2 = G Wk^T
__device__ float g_part[32 * BB * SS];         // colsum + w partials
__device__ float g_s [BB * SS];                // s = X^T 1
__device__ float g_kk[BB * SS];                // Wk s
__device__ float g_kq[BB * SS];                // Wq s
__device__ float g_w [BB * SS];                // w = attn^T Wout
__device__ float g_u [BB * SS];                // u = Wv^T w
__device__ float g_cc[BB];                     // w.bv + bout

// ---------------- warp-level bf16 MMA (baseline PTX, no arch suffix) --------
__device__ __forceinline__ void mma16816(float* c, const uint32_t* a, const uint32_t* b) {
    asm volatile(
        "mma.sync.aligned.m16n8k16.row.col.f32.bf16.bf16.f32 "
        "{%0,%1,%2,%3}, {%4,%5,%6,%7}, {%8,%9}, {%0,%1,%2,%3};"
        : "+f"(c[0]), "+f"(c[1]), "+f"(c[2]), "+f"(c[3])
        : "r"(a[0]), "r"(a[1]), "r"(a[2]), "r"(a[3]), "r"(b[0]), "r"(b[1]));
}

// smem tile geometry: [128 rows (m/n)] x [64 k] bf16, row pitch 72 bf16 (144B)
#define TROW   72
#define TBYTES (128 * TROW * 2)      // 18432
#define OFF_AHI 0
#define OFF_ALO (1 * TBYTES)
#define OFF_BHI (2 * TBYTES)
#define OFF_BLO (3 * TBYTES)
#define GRAM_SMEM (4 * TBYTES)       // 73728; stage (128*132*4=67584) overlays
#define SPITCH 132                   // fp32 stage pitch; multiple of 4 for float4

// =============================================================================
// GRAM: G = X^T X via mma.sync bf16, 3-pass hi/lo split, fp32 accum.
// 128x128 tile per CTA; upper-triangular tile pairs + mirror.
// =============================================================================
__global__ void __launch_bounds__(256)
gram_mma_kernel(const float* __restrict__ x, float* __restrict__ C) {
    const int TI[10] = {0,0,0,0,1,1,1,2,2,3};
    const int TJ[10] = {0,1,2,3,1,2,3,2,3,3};
    int pair = blockIdx.x;
    int b    = blockIdx.y;
    int m0 = TI[pair] * 128, n0 = TJ[pair] * 128;

    extern __shared__ char smem[];
    __nv_bfloat16* tAhi = (__nv_bfloat16*)(smem + OFF_AHI);
    __nv_bfloat16* tAlo = (__nv_bfloat16*)(smem + OFF_ALO);
    __nv_bfloat16* tBhi = (__nv_bfloat16*)(smem + OFF_BHI);
    __nv_bfloat16* tBlo = (__nv_bfloat16*)(smem + OFF_BLO);

    int tid = threadIdx.x;
    int wid = tid >> 5, lane = tid & 31;
    int g = lane >> 2, tg = lane & 3;

    // conversion mapping: warps 0-3 -> A tile (cols m0..), warps 4-7 -> B tile
    int isB  = wid >> 2;
    int mloc = (wid & 3) * 32 + lane;                 // 0..127
    int gcol = (isB ? n0 : m0) + mloc;
    char* chi = (char*)(isB ? tBhi : tAhi);
    char* clo = (char*)(isB ? tBlo : tAlo);
    const float* xb = x + (long)b * INCD * SS + gcol;

    // warp MMA tile: 2 (m) x 4 (n) warps, each 64x32
    int m_w = (wid & 1) * 64;
    int n_w = (wid >> 1) * 32;

    float acc[4][4][4];
    #pragma unroll
    for (int mt = 0; mt < 4; mt++)
        #pragma unroll
        for (int nt = 0; nt < 4; nt++)
            #pragma unroll
            for (int r = 0; r < 4; r++) acc[mt][nt][r] = 0.f;

    for (int c = 0; c < 32; c++) {
        // ---- convert 64 k-slices of 128 columns into hi/lo bf16 tiles
        const float* src = xb + (long)c * 64 * SS;
        #pragma unroll
        for (int kg = 0; kg < 8; kg++) {
            uint32_t hw[4], lw[4];
            #pragma unroll
            for (int jp = 0; jp < 4; jp++) {
                float v0 = src[(kg * 8 + jp * 2 + 0) * SS];
                float v1 = src[(kg * 8 + jp * 2 + 1) * SS];
                __nv_bfloat16 h0 = __float2bfloat16(v0);
                __nv_bfloat16 h1 = __float2bfloat16(v1);
                __nv_bfloat16 l0 = __float2bfloat16(v0 - __bfloat162float(h0));
                __nv_bfloat16 l1 = __float2bfloat16(v1 - __bfloat162float(h1));
                hw[jp] = (uint32_t)__bfloat16_as_ushort(h0)
                       | ((uint32_t)__bfloat16_as_ushort(h1) << 16);
                lw[jp] = (uint32_t)__bfloat16_as_ushort(l0)
                       | ((uint32_t)__bfloat16_as_ushort(l1) << 16);
            }
            int boff = mloc * 144 + kg * 16;
            *(uint4*)(chi + boff) = make_uint4(hw[0], hw[1], hw[2], hw[3]);
            *(uint4*)(clo + boff) = make_uint4(lw[0], lw[1], lw[2], lw[3]);
        }
        __syncthreads();

        // ---- MMA over this k-chunk (4 ksteps of 16)
        #pragma unroll
        for (int ks = 0; ks < 4; ks++) {
            int k0 = ks * 16;
            uint32_t bh[4][2], bl[4][2];
            #pragma unroll
            for (int nt = 0; nt < 4; nt++) {
                int nrow = n_w + nt * 8 + g;
                const char* ph = (const char*)tBhi + nrow * 144 + (k0 + tg * 2) * 2;
                const char* pl = (const char*)tBlo + nrow * 144 + (k0 + tg * 2) * 2;
                bh[nt][0] = *(const uint32_t*)ph;
                bh[nt][1] = *(const uint32_t*)(ph + 16);
                bl[nt][0] = *(const uint32_t*)pl;
                bl[nt][1] = *(const uint32_t*)(pl + 16);
            }
            #pragma unroll
            for (int mt = 0; mt < 4; mt++) {
                int mrow = m_w + mt * 16 + g;
                const char* ph = (const char*)tAhi + mrow * 144 + (k0 + tg * 2) * 2;
                const char* pl = (const char*)tAlo + mrow * 144 + (k0 + tg * 2) * 2;
                uint32_t ah[4], al[4];
                ah[0] = *(const uint32_t*)ph;
                ah[1] = *(const uint32_t*)(ph + 8 * 144);
                ah[2] = *(const uint32_t*)(ph + 16);
                ah[3] = *(const uint32_t*)(ph + 8 * 144 + 16);
                al[0] = *(const uint32_t*)pl;
                al[1] = *(const uint32_t*)(pl + 8 * 144);
                al[2] = *(const uint32_t*)(pl + 16);
                al[3] = *(const uint32_t*)(pl + 8 * 144 + 16);
                #pragma unroll
                for (int nt = 0; nt < 4; nt++) {
                    mma16816(acc[mt][nt], ah, bh[nt]);   // hi*hi
                    mma16816(acc[mt][nt], ah, bl[nt]);   // hi*lo
                    mma16816(acc[mt][nt], al, bh[nt]);   // lo*hi
                }
            }
        }
        __syncthreads();   // before next chunk's conversion overwrites tiles
    }

    // ---- epilogue: stage fp32 tile in smem (reuses tile memory), write C
    float* stage = (float*)smem;       // 128 x SPITCH(132) pitch
    #pragma unroll
    for (int mt = 0; mt < 4; mt++) {
        int r0 = m_w + mt * 16 + g;
        #pragma unroll
        for (int nt = 0; nt < 4; nt++) {
            int cc = n_w + nt * 8 + tg * 2;
            *(float2*)&stage[r0 * SPITCH + cc]       = make_float2(acc[mt][nt][0], acc[mt][nt][1]);
            *(float2*)&stage[(r0 + 8) * SPITCH + cc] = make_float2(acc[mt][nt][2], acc[mt][nt][3]);
        }
    }
    __syncthreads();

    float* Cb = C + (long)b * SS * SS;

    // normal tile: coalesced rows
    {
        int row = tid >> 1, ch = (tid & 1) * 64;
        #pragma unroll
        for (int i = 0; i < 16; i++) {
            float4 v = *(float4*)&stage[row * SPITCH + ch + i * 4];
            *(float4*)(Cb + (m0 + row) * SS + n0 + ch + i * 4) = v;
        }
    }
    // mirror tile (transpose), coalesced over m
    if (m0 != n0) {
        int i = tid & 127;
        int jb = tid >> 7;
        #pragma unroll 4
        for (int jj = 0; jj < 64; jj++) {
            int j = jj * 2 + jb;
            Cb[(n0 + j) * SS + m0 + i] = stage[i * SPITCH + j];
        }
    }
}

// ---------------- column sums: s[b,c] = sum_i X[b,i,c] ----------------------
__global__ void colsum_part_kernel(const float* __restrict__ x) {
    int slab = blockIdx.x, b = blockIdx.y, c = threadIdx.x;
    const float* p = x + ((long)b * INCD + slab * 128) * SS + c;
    float acc = 0.f;
    #pragma unroll 8
    for (int i = 0; i < 128; i++) acc += p[i * SS];
    g_part[(slab * BB + b) * SS + c] = acc;
}
__global__ void colsum_reduce_kernel() {
    int b = blockIdx.x, c = threadIdx.x;
    float acc = 0.f;
    #pragma unroll
    for (int slab = 0; slab < 16; slab++) acc += g_part[(slab * BB + b) * SS + c];
    g_s[b * SS + c] = acc;
}
__global__ void kkq_kernel(const float* __restrict__ Wk, const float* __restrict__ Wq) {
    int b = blockIdx.x, which = blockIdx.y, row = threadIdx.x;
    __shared__ float ss[SS];
    ss[row] = g_s[b * SS + row];
    __syncthreads();
    const float* wr = (which ? Wq : Wk) + row * SS;
    float acc = 0.f;
    #pragma unroll 8
    for (int c = 0; c < SS; c++) acc += wr[c] * ss[c];
    if (which) g_kq[b * SS + row] = acc;
    else       g_kk[b * SS + row] = acc;
}

// =============================================================================
// SIMT GEMM: C[m,n] = sum_k A[k*512+m] * B[n*512+k]
// =============================================================================
template <bool EPI>
__global__ void __launch_bounds__(256, 2)
gemm128_kernel(const float* __restrict__ A, long sA,
               const float* __restrict__ B,
               float* __restrict__ C, long sC,
               const float* __restrict__ e_rm, const float* __restrict__ e_rn,
               const float* __restrict__ e_bm, const float* __restrict__ e_bn,
               float e_scale)
{
    int m0 = blockIdx.y * 128, n0 = blockIdx.x * 128;
    int b  = blockIdx.z;
    A += (long)b * sA;
    C += (long)b * sC;

    __shared__ float As[2][8][132];
    __shared__ float Bs[2][8][132];

    int tid = threadIdx.x;
    int tx = tid & 15, ty = tid >> 4;
    int lr = tid >> 5, lc = (tid & 31) * 4;
    int bn = tid >> 1, bk4 = (tid & 1) * 4;

    float4 pa = *(const float4*)(A + lr * SS + m0 + lc);
    float4 pb = *(const float4*)(B + (n0 + bn) * SS + bk4);
    *(float4*)&As[0][lr][lc] = pa;
    Bs[0][bk4 + 0][bn] = pb.x; Bs[0][bk4 + 1][bn] = pb.y;
    Bs[0][bk4 + 2][bn] = pb.z; Bs[0][bk4 + 3][bn] = pb.w;
    __syncthreads();

    float acc[8][8];
    #pragma unroll
    for (int i = 0; i < 8; i++)
        #pragma unroll
        for (int j = 0; j < 8; j++) acc[i][j] = 0.f;

    const int NC = SS / 8;
    int st = 0;
    for (int c = 0; c < NC; c++) {
        if (c + 1 < NC) {
            int k0 = (c + 1) * 8;
            pa = *(const float4*)(A + (k0 + lr) * SS + m0 + lc);
            pb = *(const float4*)(B + (n0 + bn) * SS + k0 + bk4);
        }
        #pragma unroll
        for (int k = 0; k < 8; k++) {
            float4 a0 = *(const float4*)&As[st][k][ty * 4];
            float4 a1 = *(const float4*)&As[st][k][ty * 4 + 64];
            float4 b0 = *(const float4*)&Bs[st][k][tx * 4];
            float4 b1 = *(const float4*)&Bs[st][k][tx * 4 + 64];
            float av[8] = {a0.x,a0.y,a0.z,a0.w,a1.x,a1.y,a1.z,a1.w};
            float bv[8] = {b0.x,b0.y,b0.z,b0.w,b1.x,b1.y,b1.z,b1.w};
            #pragma unroll
            for (int i = 0; i < 8; i++)
                #pragma unroll
                for (int j = 0; j < 8; j++)
                    acc[i][j] += av[i] * bv[j];
        }
        if (c + 1 < NC) {
            *(float4*)&As[st ^ 1][lr][lc] = pa;
            Bs[st ^ 1][bk4 + 0][bn] = pb.x; Bs[st ^ 1][bk4 + 1][bn] = pb.y;
            Bs[st ^ 1][bk4 + 2][bn] = pb.z; Bs[st ^ 1][bk4 + 3][bn] = pb.w;
        }
        __syncthreads();
        st ^= 1;
    }

    const float* erm = EPI ? (e_rm + b * SS) : nullptr;
    const float* ern = EPI ? (e_rn + b * SS) : nullptr;

    #pragma unroll
    for (int i = 0; i < 8; i++) {
        int m = m0 + ty * 4 + (i & 3) + (i >> 2) * 64;
        float km = 0.f, bm = 0.f;
        if (EPI) { km = erm[m]; bm = e_bm[m]; }
        float vals[8];
        #pragma unroll
        for (int j = 0; j < 8; j++) {
            int n = n0 + tx * 4 + (j & 3) + (j >> 2) * 64;
            float v = acc[i][j];
            if (EPI) v += km * e_bn[n] + bm * (ern[n] + e_scale * e_bn[n]);
            vals[j] = v;
        }
        float4 v0 = {vals[0], vals[1], vals[2], vals[3]};
        float4 v1 = {vals[4], vals[5], vals[6], vals[7]};
        *(float4*)(C + m * SS + n0 + tx * 4)      = v0;
        *(float4*)(C + m * SS + n0 + tx * 4 + 64) = v1;
    }
}

// ---------------- fused softmax + partial w ----------------------------------
__global__ void softmax_w_kernel(const float* __restrict__ Wout) {
    int chunk = blockIdx.x, b = blockIdx.y, tid = threadIdx.x;
    __shared__ float red[256];
    __shared__ float wpart[SS];
    wpart[tid] = 0.f; wpart[tid + 256] = 0.f;
    __syncthreads();
    const float* Eb = g_bufA + (long)b * SS * SS;
    for (int r = 0; r < 16; r++) {
        int s = chunk * 16 + r;
        const float* row = Eb + s * SS;
        float e0 = row[tid], e1 = row[tid + 256];
        red[tid] = fmaxf(e0, e1);
        __syncthreads();
        for (int st = 128; st > 0; st >>= 1) {
            if (tid < st) red[tid] = fmaxf(red[tid], red[tid + st]);
            __syncthreads();
        }
        float mx = red[0];
        __syncthreads();
        e0 = expf(e0 - mx); e1 = expf(e1 - mx);
        red[tid] = e0 + e1;
        __syncthreads();
        for (int st = 128; st > 0; st >>= 1) {
            if (tid < st) red[tid] += red[tid + st];
            __syncthreads();
        }
        float scale = Wout[s] / red[0];
        wpart[tid]       += e0 * scale;
        wpart[tid + 256] += e1 * scale;
        __syncthreads();
    }
    float* dst = g_part + (chunk * BB + b) * SS;
    dst[tid] = wpart[tid];
    dst[tid + 256] = wpart[tid + 256];
}
__global__ void w_reduce_kernel() {
    int b = blockIdx.x, t = threadIdx.x;
    float acc = 0.f;
    #pragma unroll
    for (int chunk = 0; chunk < 32; chunk++) acc += g_part[(chunk * BB + b) * SS + t];
    g_w[b * SS + t] = acc;
}
__global__ void u_kernel(const float* __restrict__ Wv, const float* __restrict__ bv,
                         const float* __restrict__ bout) {
    int b = blockIdx.x, c = threadIdx.x;
    __shared__ float ws[SS];
    __shared__ float red[SS];
    ws[c] = g_w[b * SS + c];
    __syncthreads();
    float acc = 0.f;
    #pragma unroll 8
    for (int t = 0; t < SS; t++) acc += ws[t] * Wv[t * SS + c];
    g_u[b * SS + c] = acc;
    red[c] = ws[c] * bv[c];
    __syncthreads();
    for (int s = 256; s > 0; s >>= 1) {
        if (c < s) red[c] += red[c + s];
        __syncthreads();
    }
    if (c == 0) g_cc[b] = red[0] + bout[0];
}
__global__ void out_kernel(const float* __restrict__ x, float* __restrict__ out) {
    int b = blockIdx.y, i0 = blockIdx.x * 8, tid = threadIdx.x;
    __shared__ float us[SS];
    us[tid] = g_u[b * SS + tid];
    us[tid + 256] = g_u[b * SS + tid + 256];
    __syncthreads();
    int warp = tid >> 5, lane = tid & 31;
    int i = i0 + warp;
    const float* xr = x + ((long)b * INCD + i) * SS;
    float acc = 0.f;
    #pragma unroll
    for (int s = lane; s < SS; s += 32) acc += xr[s] * us[s];
    #pragma unroll
    for (int o = 16; o > 0; o >>= 1) acc += __shfl_xor_sync(0xffffffffu, acc, o);
    if (lane == 0) out[(long)b * INCD + i] = acc + g_cc[b];
}

// ---------------- launch -----------------------------------------------------
extern "C" void kernel_launch(void* const* d_in, const int* in_sizes, int n_in,
                              void* d_out, int out_size) {
    const float* x    = (const float*)d_in[0];
    const float* Wq   = (const float*)d_in[1];
    const float* bq   = (const float*)d_in[2];
    const float* Wk   = (const float*)d_in[3];
    const float* bk   = (const float*)d_in[4];
    const float* Wv   = (const float*)d_in[5];
    const float* bv   = (const float*)d_in[6];
    const float* Wout = (const float*)d_in[7];
    const float* bout = (const float*)d_in[8];
    float* out = (float*)d_out;

    void *pA, *pB, *pkk, *pkq;
    cudaGetSymbolAddress(&pA,  g_bufA);
    cudaGetSymbolAddress(&pB,  g_bufB);
    cudaGetSymbolAddress(&pkk, g_kk);
    cudaGetSymbolAddress(&pkq, g_kq);
    float* bufA = (float*)pA;
    float* bufB = (float*)pB;
    float* kk   = (float*)pkk;
    float* kq   = (float*)pkq;

    const long sBatch = (long)SS * SS;

    cudaFuncSetAttribute(gram_mma_kernel,
                         cudaFuncAttributeMaxDynamicSharedMemorySize, GRAM_SMEM);

    // 1) column sums -> s, then kk = Wk s, kq = Wq s
    colsum_part_kernel<<<dim3(16, BB), SS>>>(x);
    colsum_reduce_kernel<<<BB, SS>>>();
    kkq_kernel<<<dim3(BB, 2), SS>>>(Wk, Wq);

    // 2) G = X^T X via mma.sync bf16 3-pass -> bufA
    gram_mma_kernel<<<dim3(10, BB), 256, GRAM_SMEM>>>(x, bufA);

    // 3) M2 = G Wk^T -> bufB
    gemm128_kernel<false><<<dim3(4, 4, BB), 256>>>(
        bufA, sBatch, Wk, bufB, sBatch,
        nullptr, nullptr, nullptr, nullptr, 0.f);

    // 4) E = M2^T Wq^T (= Wk G Wq^T) + rank-1 -> bufA
    gemm128_kernel<true><<<dim3(4, 4, BB), 256>>>(
        bufB, sBatch, Wq, bufA, sBatch,
        kk, kq, bk, bq, (float)INCD);

    // 5) fused softmax + w partials, then reduce
    softmax_w_kernel<<<dim3(32, BB), 256>>>(Wout);
    w_reduce_kernel<<<BB, SS>>>();

    // 6) u = Wv^T w, cc = w.bv + bout
    u_kernel<<<BB, SS>>>(Wv, bv, bout);

    // 7) out = X u + cc
    out_kernel<<<dim3(INCD / 8, BB), 256>>>(x, out);
}

// round 13
// speedup vs baseline: 1.7315x; 1.0745x over previous
#include <cuda_runtime.h>
#include <cuda_bf16.h>
#include <math.h>
#include <stdint.h>

#define BB   32
#define INCD 2048
#define SS   512

// ---------------- scratch (static device globals; no allocs) ----------------
__device__ float g_bufA[(long)BB * SS * SS];   // G, then E (in place)
__device__ float g_bufB[(long)BB * SS * SS];   // M2 = G Wk^T
__device__ float g_part[32 * BB * SS];         // colsum + w partials
__device__ float g_s [BB * SS];                // s = X^T 1
__device__ float g_kk[BB * SS];                // Wk s
__device__ float g_kq[BB * SS];                // Wq s
__device__ float g_w [BB * SS];                // w = attn^T Wout
__device__ float g_u [BB * SS];                // u = Wv^T w
__device__ float g_cc[BB];                     // w.bv + bout

// ---------------- warp-level bf16 MMA (baseline PTX, no arch suffix) --------
__device__ __forceinline__ void mma16816(float* c, const uint32_t* a, const uint32_t* b) {
    asm volatile(
        "mma.sync.aligned.m16n8k16.row.col.f32.bf16.bf16.f32 "
        "{%0,%1,%2,%3}, {%4,%5,%6,%7}, {%8,%9}, {%0,%1,%2,%3};"
        : "+f"(c[0]), "+f"(c[1]), "+f"(c[2]), "+f"(c[3])
        : "r"(a[0]), "r"(a[1]), "r"(a[2]), "r"(a[3]), "r"(b[0]), "r"(b[1]));
}

__device__ __forceinline__ void pack_hilo(float v0, float v1, uint32_t& hw, uint32_t& lw) {
    __nv_bfloat16 h0 = __float2bfloat16(v0);
    __nv_bfloat16 h1 = __float2bfloat16(v1);
    __nv_bfloat16 l0 = __float2bfloat16(v0 - __bfloat162float(h0));
    __nv_bfloat16 l1 = __float2bfloat16(v1 - __bfloat162float(h1));
    hw = (uint32_t)__bfloat16_as_ushort(h0) | ((uint32_t)__bfloat16_as_ushort(h1) << 16);
    lw = (uint32_t)__bfloat16_as_ushort(l0) | ((uint32_t)__bfloat16_as_ushort(l1) << 16);
}

// smem tile geometry: [128 rows (m/n)] x [64 k] bf16, row pitch 72 bf16 (144B)
#define TBYTES (128 * 72 * 2)        // 18432
#define OFF_AHI 0
#define OFF_ALO (1 * TBYTES)
#define OFF_BHI (2 * TBYTES)
#define OFF_BLO (3 * TBYTES)
#define GRAM_SMEM (4 * TBYTES)       // 73728; stage (128*132*4=67584) overlays
#define SPITCH 132                   // fp32 stage pitch; multiple of 4 for float4

// =============================================================================
// GRAM: G = X^T X via mma.sync bf16, 3-pass hi/lo split, fp32 accum.
// =============================================================================
__global__ void __launch_bounds__(256)
gram_mma_kernel(const float* __restrict__ x, float* __restrict__ C) {
    const int TI[10] = {0,0,0,0,1,1,1,2,2,3};
    const int TJ[10] = {0,1,2,3,1,2,3,2,3,3};
    int pair = blockIdx.x;
    int b    = blockIdx.y;
    int m0 = TI[pair] * 128, n0 = TJ[pair] * 128;

    extern __shared__ char smem[];
    int tid = threadIdx.x;
    int wid = tid >> 5, lane = tid & 31;
    int g = lane >> 2, tg = lane & 3;

    int isB  = wid >> 2;
    int mloc = (wid & 3) * 32 + lane;
    int gcol = (isB ? n0 : m0) + mloc;
    char* chi = smem + (isB ? OFF_BHI : OFF_AHI);
    char* clo = smem + (isB ? OFF_BLO : OFF_ALO);
    const float* xb = x + (long)b * INCD * SS + gcol;

    int m_w = (wid & 1) * 64;
    int n_w = (wid >> 1) * 32;

    float acc[4][4][4];
    #pragma unroll
    for (int mt = 0; mt < 4; mt++)
        #pragma unroll
        for (int nt = 0; nt < 4; nt++)
            #pragma unroll
            for (int r = 0; r < 4; r++) acc[mt][nt][r] = 0.f;

    for (int c = 0; c < 32; c++) {
        const float* src = xb + (long)c * 64 * SS;
        #pragma unroll
        for (int kg = 0; kg < 8; kg++) {
            uint32_t hw[4], lw[4];
            #pragma unroll
            for (int jp = 0; jp < 4; jp++)
                pack_hilo(src[(kg * 8 + jp * 2 + 0) * SS],
                          src[(kg * 8 + jp * 2 + 1) * SS], hw[jp], lw[jp]);
            int boff = mloc * 144 + kg * 16;
            *(uint4*)(chi + boff) = make_uint4(hw[0], hw[1], hw[2], hw[3]);
            *(uint4*)(clo + boff) = make_uint4(lw[0], lw[1], lw[2], lw[3]);
        }
        __syncthreads();

        #pragma unroll
        for (int ks = 0; ks < 4; ks++) {
            int k0 = ks * 16;
            uint32_t bh[4][2], bl[4][2];
            #pragma unroll
            for (int nt = 0; nt < 4; nt++) {
                int nrow = n_w + nt * 8 + g;
                const char* ph = smem + OFF_BHI + nrow * 144 + (k0 + tg * 2) * 2;
                const char* pl = smem + OFF_BLO + nrow * 144 + (k0 + tg * 2) * 2;
                bh[nt][0] = *(const uint32_t*)ph;
                bh[nt][1] = *(const uint32_t*)(ph + 16);
                bl[nt][0] = *(const uint32_t*)pl;
                bl[nt][1] = *(const uint32_t*)(pl + 16);
            }
            #pragma unroll
            for (int mt = 0; mt < 4; mt++) {
                int mrow = m_w + mt * 16 + g;
                const char* ph = smem + OFF_AHI + mrow * 144 + (k0 + tg * 2) * 2;
                const char* pl = smem + OFF_ALO + mrow * 144 + (k0 + tg * 2) * 2;
                uint32_t ah[4], al[4];
                ah[0] = *(const uint32_t*)ph;
                ah[1] = *(const uint32_t*)(ph + 8 * 144);
                ah[2] = *(const uint32_t*)(ph + 16);
                ah[3] = *(const uint32_t*)(ph + 8 * 144 + 16);
                al[0] = *(const uint32_t*)pl;
                al[1] = *(const uint32_t*)(pl + 8 * 144);
                al[2] = *(const uint32_t*)(pl + 16);
                al[3] = *(const uint32_t*)(pl + 8 * 144 + 16);
                #pragma unroll
                for (int nt = 0; nt < 4; nt++) {
                    mma16816(acc[mt][nt], ah, bh[nt]);
                    mma16816(acc[mt][nt], ah, bl[nt]);
                    mma16816(acc[mt][nt], al, bh[nt]);
                }
            }
        }
        __syncthreads();
    }

    float* stage = (float*)smem;
    #pragma unroll
    for (int mt = 0; mt < 4; mt++) {
        int r0 = m_w + mt * 16 + g;
        #pragma unroll
        for (int nt = 0; nt < 4; nt++) {
            int cc = n_w + nt * 8 + tg * 2;
            *(float2*)&stage[r0 * SPITCH + cc]       = make_float2(acc[mt][nt][0], acc[mt][nt][1]);
            *(float2*)&stage[(r0 + 8) * SPITCH + cc] = make_float2(acc[mt][nt][2], acc[mt][nt][3]);
        }
    }
    __syncthreads();

    float* Cb = C + (long)b * SS * SS;
    {
        int row = tid >> 1, ch = (tid & 1) * 64;
        #pragma unroll
        for (int i = 0; i < 16; i++) {
            float4 v = *(float4*)&stage[row * SPITCH + ch + i * 4];
            *(float4*)(Cb + (m0 + row) * SS + n0 + ch + i * 4) = v;
        }
    }
    if (m0 != n0) {
        int i = tid & 127;
        int jb = tid >> 7;
        #pragma unroll 4
        for (int jj = 0; jj < 64; jj++) {
            int j = jj * 2 + jb;
            Cb[(n0 + j) * SS + m0 + i] = stage[i * SPITCH + j];
        }
    }
}

// =============================================================================
// HMMA GEMM: C[m,n] = sum_k A[k*512+m] * B[n*512+k], K=512, 3-pass bf16.
// A batch-strided (G or M2, m-contiguous rows), B = weight (k-contiguous rows).
// =============================================================================
template <bool EPI>
__global__ void __launch_bounds__(256)
gemm_mma_kernel(const float* __restrict__ A, long sA,
                const float* __restrict__ B,
                float* __restrict__ C, long sC,
                const float* __restrict__ e_rm, const float* __restrict__ e_rn,
                const float* __restrict__ e_bm, const float* __restrict__ e_bn,
                float e_scale)
{
    int m0 = blockIdx.y * 128, n0 = blockIdx.x * 128;
    int b  = blockIdx.z;
    A += (long)b * sA;

    extern __shared__ char smem[];
    int tid = threadIdx.x;
    int wid = tid >> 5, lane = tid & 31;
    int g = lane >> 2, tg = lane & 3;

    int isB  = wid >> 2;
    int mloc = (wid & 3) * 32 + lane;
    char* chi = smem + (isB ? OFF_BHI : OFF_AHI);
    char* clo = smem + (isB ? OFF_BLO : OFF_ALO);
    const float* asrc = A + m0 + mloc;             // A[k][m0+mloc], stride SS over k
    const float* bsrc = B + (long)(n0 + mloc) * SS; // B[n0+mloc][k], contiguous k

    int m_w = (wid & 1) * 64;
    int n_w = (wid >> 1) * 32;

    float acc[4][4][4];
    #pragma unroll
    for (int mt = 0; mt < 4; mt++)
        #pragma unroll
        for (int nt = 0; nt < 4; nt++)
            #pragma unroll
            for (int r = 0; r < 4; r++) acc[mt][nt][r] = 0.f;

    for (int c = 0; c < 8; c++) {                  // K = 512 in 64-chunks
        if (!isB) {
            const float* src = asrc + (long)c * 64 * SS;
            #pragma unroll
            for (int kg = 0; kg < 8; kg++) {
                uint32_t hw[4], lw[4];
                #pragma unroll
                for (int jp = 0; jp < 4; jp++)
                    pack_hilo(src[(kg * 8 + jp * 2 + 0) * SS],
                              src[(kg * 8 + jp * 2 + 1) * SS], hw[jp], lw[jp]);
                int boff = mloc * 144 + kg * 16;
                *(uint4*)(chi + boff) = make_uint4(hw[0], hw[1], hw[2], hw[3]);
                *(uint4*)(clo + boff) = make_uint4(lw[0], lw[1], lw[2], lw[3]);
            }
        } else {
            const float* src = bsrc + c * 64;
            #pragma unroll
            for (int kg = 0; kg < 8; kg++) {
                float4 v0 = *(const float4*)(src + kg * 8);
                float4 v1 = *(const float4*)(src + kg * 8 + 4);
                uint32_t hw[4], lw[4];
                pack_hilo(v0.x, v0.y, hw[0], lw[0]);
                pack_hilo(v0.z, v0.w, hw[1], lw[1]);
                pack_hilo(v1.x, v1.y, hw[2], lw[2]);
                pack_hilo(v1.z, v1.w, hw[3], lw[3]);
                int boff = mloc * 144 + kg * 16;
                *(uint4*)(chi + boff) = make_uint4(hw[0], hw[1], hw[2], hw[3]);
                *(uint4*)(clo + boff) = make_uint4(lw[0], lw[1], lw[2], lw[3]);
            }
        }
        __syncthreads();

        #pragma unroll
        for (int ks = 0; ks < 4; ks++) {
            int k0 = ks * 16;
            uint32_t bh[4][2], bl[4][2];
            #pragma unroll
            for (int nt = 0; nt < 4; nt++) {
                int nrow = n_w + nt * 8 + g;
                const char* ph = smem + OFF_BHI + nrow * 144 + (k0 + tg * 2) * 2;
                const char* pl = smem + OFF_BLO + nrow * 144 + (k0 + tg * 2) * 2;
                bh[nt][0] = *(const uint32_t*)ph;
                bh[nt][1] = *(const uint32_t*)(ph + 16);
                bl[nt][0] = *(const uint32_t*)pl;
                bl[nt][1] = *(const uint32_t*)(pl + 16);
            }
            #pragma unroll
            for (int mt = 0; mt < 4; mt++) {
                int mrow = m_w + mt * 16 + g;
                const char* ph = smem + OFF_AHI + mrow * 144 + (k0 + tg * 2) * 2;
                const char* pl = smem + OFF_ALO + mrow * 144 + (k0 + tg * 2) * 2;
                uint32_t ah[4], al[4];
                ah[0] = *(const uint32_t*)ph;
                ah[1] = *(const uint32_t*)(ph + 8 * 144);
                ah[2] = *(const uint32_t*)(ph + 16);
                ah[3] = *(const uint32_t*)(ph + 8 * 144 + 16);
                al[0] = *(const uint32_t*)pl;
                al[1] = *(const uint32_t*)(pl + 8 * 144);
                al[2] = *(const uint32_t*)(pl + 16);
                al[3] = *(const uint32_t*)(pl + 8 * 144 + 16);
                #pragma unroll
                for (int nt = 0; nt < 4; nt++) {
                    mma16816(acc[mt][nt], ah, bh[nt]);
                    mma16816(acc[mt][nt], ah, bl[nt]);
                    mma16816(acc[mt][nt], al, bh[nt]);
                }
            }
        }
        __syncthreads();
    }

    float* stage = (float*)smem;
    #pragma unroll
    for (int mt = 0; mt < 4; mt++) {
        int r0 = m_w + mt * 16 + g;
        #pragma unroll
        for (int nt = 0; nt < 4; nt++) {
            int cc = n_w + nt * 8 + tg * 2;
            *(float2*)&stage[r0 * SPITCH + cc]       = make_float2(acc[mt][nt][0], acc[mt][nt][1]);
            *(float2*)&stage[(r0 + 8) * SPITCH + cc] = make_float2(acc[mt][nt][2], acc[mt][nt][3]);
        }
    }
    __syncthreads();

    float* Cb = C + (long)b * sC;
    int row = tid >> 1, ch = (tid & 1) * 64;
    int m = m0 + row;
    float km = 0.f, bm = 0.f;
    if (EPI) { km = e_rm[b * SS + m]; bm = e_bm[m]; }
    #pragma unroll
    for (int i = 0; i < 16; i++) {
        float4 v = *(float4*)&stage[row * SPITCH + ch + i * 4];
        if (EPI) {
            int n = n0 + ch + i * 4;
            v.x += km * e_bn[n + 0] + bm * (e_rn[b * SS + n + 0] + e_scale * e_bn[n + 0]);
            v.y += km * e_bn[n + 1] + bm * (e_rn[b * SS + n + 1] + e_scale * e_bn[n + 1]);
            v.z += km * e_bn[n + 2] + bm * (e_rn[b * SS + n + 2] + e_scale * e_bn[n + 2]);
            v.w += km * e_bn[n + 3] + bm * (e_rn[b * SS + n + 3] + e_scale * e_bn[n + 3]);
        }
        *(float4*)(Cb + (long)m * SS + n0 + ch + i * 4) = v;
    }
}

// ---------------- column sums: s[b,c] = sum_i X[b,i,c] ----------------------
__global__ void colsum_part_kernel(const float* __restrict__ x) {
    int slab = blockIdx.x, b = blockIdx.y, c = threadIdx.x;
    const float* p = x + ((long)b * INCD + slab * 128) * SS + c;
    float acc = 0.f;
    #pragma unroll 8
    for (int i = 0; i < 128; i++) acc += p[i * SS];
    g_part[(slab * BB + b) * SS + c] = acc;
}
__global__ void colsum_reduce_kernel() {
    int b = blockIdx.x, c = threadIdx.x;
    float acc = 0.f;
    #pragma unroll
    for (int slab = 0; slab < 16; slab++) acc += g_part[(slab * BB + b) * SS + c];
    g_s[b * SS + c] = acc;
}
__global__ void kkq_kernel(const float* __restrict__ Wk, const float* __restrict__ Wq) {
    int b = blockIdx.x, which = blockIdx.y, row = threadIdx.x;
    __shared__ float ss[SS];
    ss[row] = g_s[b * SS + row];
    __syncthreads();
    const float* wr = (which ? Wq : Wk) + row * SS;
    float acc = 0.f;
    #pragma unroll 8
    for (int c = 0; c < SS; c++) acc += wr[c] * ss[c];
    if (which) g_kq[b * SS + row] = acc;
    else       g_kk[b * SS + row] = acc;
}

// ---------------- fused softmax + partial w ----------------------------------
__global__ void softmax_w_kernel(const float* __restrict__ Wout) {
    int chunk = blockIdx.x, b = blockIdx.y, tid = threadIdx.x;
    __shared__ float red[256];
    __shared__ float wpart[SS];
    wpart[tid] = 0.f; wpart[tid + 256] = 0.f;
    __syncthreads();
    const float* Eb = g_bufA + (long)b * SS * SS;
    for (int r = 0; r < 16; r++) {
        int s = chunk * 16 + r;
        const float* row = Eb + s * SS;
        float e0 = row[tid], e1 = row[tid + 256];
        red[tid] = fmaxf(e0, e1);
        __syncthreads();
        for (int st = 128; st > 0; st >>= 1) {
            if (tid < st) red[tid] = fmaxf(red[tid], red[tid + st]);
            __syncthreads();
        }
        float mx = red[0];
        __syncthreads();
        e0 = expf(e0 - mx); e1 = expf(e1 - mx);
        red[tid] = e0 + e1;
        __syncthreads();
        for (int st = 128; st > 0; st >>= 1) {
            if (tid < st) red[tid] += red[tid + st];
            __syncthreads();
        }
        float scale = Wout[s] / red[0];
        wpart[tid]       += e0 * scale;
        wpart[tid + 256] += e1 * scale;
        __syncthreads();
    }
    float* dst = g_part + (chunk * BB + b) * SS;
    dst[tid] = wpart[tid];
    dst[tid + 256] = wpart[tid + 256];
}
__global__ void w_reduce_kernel() {
    int b = blockIdx.x, t = threadIdx.x;
    float acc = 0.f;
    #pragma unroll
    for (int chunk = 0; chunk < 32; chunk++) acc += g_part[(chunk * BB + b) * SS + t];
    g_w[b * SS + t] = acc;
}
__global__ void u_kernel(const float* __restrict__ Wv, const float* __restrict__ bv,
                         const float* __restrict__ bout) {
    int b = blockIdx.x, c = threadIdx.x;
    __shared__ float ws[SS];
    __shared__ float red[SS];
    ws[c] = g_w[b * SS + c];
    __syncthreads();
    float acc = 0.f;
    #pragma unroll 8
    for (int t = 0; t < SS; t++) acc += ws[t] * Wv[t * SS + c];
    g_u[b * SS + c] = acc;
    red[c] = ws[c] * bv[c];
    __syncthreads();
    for (int s = 256; s > 0; s >>= 1) {
        if (c < s) red[c] += red[c + s];
        __syncthreads();
    }
    if (c == 0) g_cc[b] = red[0] + bout[0];
}
__global__ void out_kernel(const float* __restrict__ x, float* __restrict__ out) {
    int b = blockIdx.y, i0 = blockIdx.x * 8, tid = threadIdx.x;
    __shared__ float us[SS];
    us[tid] = g_u[b * SS + tid];
    us[tid + 256] = g_u[b * SS + tid + 256];
    __syncthreads();
    int warp = tid >> 5, lane = tid & 31;
    int i = i0 + warp;
    const float* xr = x + ((long)b * INCD + i) * SS;
    float acc = 0.f;
    #pragma unroll
    for (int s = lane; s < SS; s += 32) acc += xr[s] * us[s];
    #pragma unroll
    for (int o = 16; o > 0; o >>= 1) acc += __shfl_xor_sync(0xffffffffu, acc, o);
    if (lane == 0) out[(long)b * INCD + i] = acc + g_cc[b];
}

// ---------------- launch -----------------------------------------------------
extern "C" void kernel_launch(void* const* d_in, const int* in_sizes, int n_in,
                              void* d_out, int out_size) {
    const float* x    = (const float*)d_in[0];
    const float* Wq   = (const float*)d_in[1];
    const float* bq   = (const float*)d_in[2];
    const float* Wk   = (const float*)d_in[3];
    const float* bk   = (const float*)d_in[4];
    const float* Wv   = (const float*)d_in[5];
    const float* bv   = (const float*)d_in[6];
    const float* Wout = (const float*)d_in[7];
    const float* bout = (const float*)d_in[8];
    float* out = (float*)d_out;

    void *pA, *pB, *pkk, *pkq;
    cudaGetSymbolAddress(&pA,  g_bufA);
    cudaGetSymbolAddress(&pB,  g_bufB);
    cudaGetSymbolAddress(&pkk, g_kk);
    cudaGetSymbolAddress(&pkq, g_kq);
    float* bufA = (float*)pA;
    float* bufB = (float*)pB;
    float* kk   = (float*)pkk;
    float* kq   = (float*)pkq;

    const long sBatch = (long)SS * SS;

    cudaFuncSetAttribute(gram_mma_kernel,
                         cudaFuncAttributeMaxDynamicSharedMemorySize, GRAM_SMEM);
    cudaFuncSetAttribute(gemm_mma_kernel<false>,
                         cudaFuncAttributeMaxDynamicSharedMemorySize, GRAM_SMEM);
    cudaFuncSetAttribute(gemm_mma_kernel<true>,
                         cudaFuncAttributeMaxDynamicSharedMemorySize, GRAM_SMEM);

    // 1) column sums -> s, then kk = Wk s, kq = Wq s
    colsum_part_kernel<<<dim3(16, BB), SS>>>(x);
    colsum_reduce_kernel<<<BB, SS>>>();
    kkq_kernel<<<dim3(BB, 2), SS>>>(Wk, Wq);

    // 2) G = X^T X via mma.sync bf16 3-pass -> bufA
    gram_mma_kernel<<<dim3(10, BB), 256, GRAM_SMEM>>>(x, bufA);

    // 3) M2 = G Wk^T -> bufB (HMMA)
    gemm_mma_kernel<false><<<dim3(4, 4, BB), 256, GRAM_SMEM>>>(
        bufA, sBatch, Wk, bufB, sBatch,
        nullptr, nullptr, nullptr, nullptr, 0.f);

    // 4) E = M2^T Wq^T (= Wk G Wq^T) + rank-1 -> bufA (HMMA)
    gemm_mma_kernel<true><<<dim3(4, 4, BB), 256, GRAM_SMEM>>>(
        bufB, sBatch, Wq, bufA, sBatch,
        kk, kq, bk, bq, (float)INCD);

    // 5) fused softmax + w partials, then reduce
    softmax_w_kernel<<<dim3(32, BB), 256>>>(Wout);
    w_reduce_kernel<<<BB, SS>>>();

    // 6) u = Wv^T w, cc = w.bv + bout
    u_kernel<<<BB, SS>>>(Wv, bv, bout);

    // 7) out = X u + cc
    out_kernel<<<dim3(INCD / 8, BB), 256>>>(x, out);
}

// round 14
// speedup vs baseline: 2.0469x; 1.1822x over previous
#include <cuda_runtime.h>
#include <cuda_bf16.h>
#include <math.h>
#include <stdint.h>

#define BB   32
#define INCD 2048
#define SS   512

// ---------------- scratch (static device globals; no allocs) ----------------
__device__ float g_bufA[(long)BB * SS * SS];   // G, then E (in place)
__device__ float g_bufB[(long)BB * SS * SS];   // M2 = G Wk^T
__device__ float g_part[32 * BB * SS];         // colsum + w partials
__device__ float g_s [BB * SS];                // s = X^T 1
__device__ float g_kk[BB * SS];                // Wk s
__device__ float g_kq[BB * SS];                // Wq s
__device__ float g_w [BB * SS];                // w = attn^T Wout
__device__ float g_u [BB * SS];                // u = Wv^T w
__device__ float g_cc[BB];                     // w.bv + bout

// ---------------- warp-level bf16 MMA (baseline PTX, no arch suffix) --------
__device__ __forceinline__ void mma16816(float* c, const uint32_t* a, const uint32_t* b) {
    asm volatile(
        "mma.sync.aligned.m16n8k16.row.col.f32.bf16.bf16.f32 "
        "{%0,%1,%2,%3}, {%4,%5,%6,%7}, {%8,%9}, {%0,%1,%2,%3};"
        : "+f"(c[0]), "+f"(c[1]), "+f"(c[2]), "+f"(c[3])
        : "r"(a[0]), "r"(a[1]), "r"(a[2]), "r"(a[3]), "r"(b[0]), "r"(b[1]));
}

__device__ __forceinline__ void pack_hilo(float v0, float v1, uint32_t& hw, uint32_t& lw) {
    __nv_bfloat16 h0 = __float2bfloat16(v0);
    __nv_bfloat16 h1 = __float2bfloat16(v1);
    __nv_bfloat16 l0 = __float2bfloat16(v0 - __bfloat162float(h0));
    __nv_bfloat16 l1 = __float2bfloat16(v1 - __bfloat162float(h1));
    hw = (uint32_t)__bfloat16_as_ushort(h0) | ((uint32_t)__bfloat16_as_ushort(h1) << 16);
    lw = (uint32_t)__bfloat16_as_ushort(l0) | ((uint32_t)__bfloat16_as_ushort(l1) << 16);
}

// tile geometry: [128 rows] x [64 k] bf16, row pitch 72 bf16 (144B)
#define TBYTES  (128 * 72 * 2)       // 18432
#define OFF_AHI 0
#define OFF_ALO (1 * TBYTES)
#define OFF_BHI (2 * TBYTES)
#define OFF_BLO (3 * TBYTES)
#define SETBYTES (4 * TBYTES)        // one complete tile set (A,B)x(hi,lo)
#define MMA_SMEM (2 * SETBYTES)      // 147456, double buffered
#define SPITCH 132                   // fp32 stage pitch (overlays tiles)

// ---- producer: convert one 64-k chunk of a column-block into tile set ------
// src points at the thread's column; values at src[k*SS], k = 0..63
__device__ __forceinline__ void produce_strided(char* chi, char* clo, int mloc,
                                                const float* src) {
    #pragma unroll
    for (int kg = 0; kg < 8; kg++) {
        uint32_t hw[4], lw[4];
        #pragma unroll
        for (int jp = 0; jp < 4; jp++)
            pack_hilo(src[(kg * 8 + jp * 2 + 0) * SS],
                      src[(kg * 8 + jp * 2 + 1) * SS], hw[jp], lw[jp]);
        int boff = mloc * 144 + kg * 16;
        *(uint4*)(chi + boff) = make_uint4(hw[0], hw[1], hw[2], hw[3]);
        *(uint4*)(clo + boff) = make_uint4(lw[0], lw[1], lw[2], lw[3]);
    }
}
// src points at 64 contiguous floats
__device__ __forceinline__ void produce_contig(char* chi, char* clo, int mloc,
                                               const float* src) {
    #pragma unroll
    for (int kg = 0; kg < 8; kg++) {
        float4 v0 = *(const float4*)(src + kg * 8);
        float4 v1 = *(const float4*)(src + kg * 8 + 4);
        uint32_t hw[4], lw[4];
        pack_hilo(v0.x, v0.y, hw[0], lw[0]);
        pack_hilo(v0.z, v0.w, hw[1], lw[1]);
        pack_hilo(v1.x, v1.y, hw[2], lw[2]);
        pack_hilo(v1.z, v1.w, hw[3], lw[3]);
        int boff = mloc * 144 + kg * 16;
        *(uint4*)(chi + boff) = make_uint4(hw[0], hw[1], hw[2], hw[3]);
        *(uint4*)(clo + boff) = make_uint4(lw[0], lw[1], lw[2], lw[3]);
    }
}

// ---- consumer: 3-pass MMA over one 64-k tile set ----------------------------
__device__ __forceinline__ void consume_chunk(const char* base, int m_w, int n_w,
                                              int g, int tg, float acc[4][4][4]) {
    #pragma unroll
    for (int ks = 0; ks < 4; ks++) {
        int k0 = ks * 16;
        uint32_t bh[4][2], bl[4][2];
        #pragma unroll
        for (int nt = 0; nt < 4; nt++) {
            int nrow = n_w + nt * 8 + g;
            const char* ph = base + OFF_BHI + nrow * 144 + (k0 + tg * 2) * 2;
            const char* pl = base + OFF_BLO + nrow * 144 + (k0 + tg * 2) * 2;
            bh[nt][0] = *(const uint32_t*)ph;
            bh[nt][1] = *(const uint32_t*)(ph + 16);
            bl[nt][0] = *(const uint32_t*)pl;
            bl[nt][1] = *(const uint32_t*)(pl + 16);
        }
        #pragma unroll
        for (int mt = 0; mt < 4; mt++) {
            int mrow = m_w + mt * 16 + g;
            const char* ph = base + OFF_AHI + mrow * 144 + (k0 + tg * 2) * 2;
            const char* pl = base + OFF_ALO + mrow * 144 + (k0 + tg * 2) * 2;
            uint32_t ah[4], al[4];
            ah[0] = *(const uint32_t*)ph;
            ah[1] = *(const uint32_t*)(ph + 8 * 144);
            ah[2] = *(const uint32_t*)(ph + 16);
            ah[3] = *(const uint32_t*)(ph + 8 * 144 + 16);
            al[0] = *(const uint32_t*)pl;
            al[1] = *(const uint32_t*)(pl + 8 * 144);
            al[2] = *(const uint32_t*)(pl + 16);
            al[3] = *(const uint32_t*)(pl + 8 * 144 + 16);
            #pragma unroll
            for (int nt = 0; nt < 4; nt++) {
                mma16816(acc[mt][nt], ah, bh[nt]);
                mma16816(acc[mt][nt], ah, bl[nt]);
                mma16816(acc[mt][nt], al, bh[nt]);
            }
        }
    }
}

// =============================================================================
// GRAM: G = X^T X, warp-specialized (8 producer + 8 consumer warps),
// double-buffered 64-k chunks, 3-pass bf16 HMMA, fp32 accum.
// =============================================================================
__global__ void __launch_bounds__(512)
gram_mma_kernel(const float* __restrict__ x, float* __restrict__ C) {
    const int TI[10] = {0,0,0,0,1,1,1,2,2,3};
    const int TJ[10] = {0,1,2,3,1,2,3,2,3,3};
    int pair = blockIdx.x;
    int b    = blockIdx.y;
    int m0 = TI[pair] * 128, n0 = TJ[pair] * 128;

    extern __shared__ char smem[];
    int tid = threadIdx.x;
    int wid = tid >> 5, lane = tid & 31;
    bool producer = (wid < 8);

    // producer mapping
    int isB  = (wid >> 2) & 1;
    int mloc = (wid & 3) * 32 + lane;
    int toff = isB ? OFF_BHI : OFF_AHI;
    const float* xb = x + (long)b * INCD * SS + (isB ? n0 : m0) + mloc;

    // consumer mapping
    int cwid = wid - 8;
    int m_w = (cwid & 1) * 64;
    int n_w = (cwid >> 1) * 32;
    int g = lane >> 2, tg = lane & 3;

    float acc[4][4][4];
    #pragma unroll
    for (int mt = 0; mt < 4; mt++)
        #pragma unroll
        for (int nt = 0; nt < 4; nt++)
            #pragma unroll
            for (int r = 0; r < 4; r++) acc[mt][nt][r] = 0.f;

    const int NC = INCD / 64;   // 32
    if (producer)
        produce_strided(smem + toff, smem + toff + TBYTES, mloc, xb);
    __syncthreads();

    for (int c = 0; c < NC; c++) {
        if (producer) {
            if (c + 1 < NC) {
                char* base = smem + ((c + 1) & 1) * SETBYTES + toff;
                produce_strided(base, base + TBYTES, mloc, xb + (long)(c + 1) * 64 * SS);
            }
        } else {
            consume_chunk(smem + (c & 1) * SETBYTES, m_w, n_w, g, tg, acc);
        }
        __syncthreads();
    }

    // ---- epilogue: consumers stage fp32 tile; everyone writes out
    float* stage = (float*)smem;
    if (!producer) {
        #pragma unroll
        for (int mt = 0; mt < 4; mt++) {
            int r0 = m_w + mt * 16 + g;
            #pragma unroll
            for (int nt = 0; nt < 4; nt++) {
                int cc = n_w + nt * 8 + tg * 2;
                *(float2*)&stage[r0 * SPITCH + cc]       = make_float2(acc[mt][nt][0], acc[mt][nt][1]);
                *(float2*)&stage[(r0 + 8) * SPITCH + cc] = make_float2(acc[mt][nt][2], acc[mt][nt][3]);
            }
        }
    }
    __syncthreads();

    float* Cb = C + (long)b * SS * SS;
    {
        int row = tid >> 2, ch = (tid & 3) * 32;
        #pragma unroll
        for (int i = 0; i < 8; i++) {
            float4 v = *(float4*)&stage[row * SPITCH + ch + i * 4];
            *(float4*)(Cb + (m0 + row) * SS + n0 + ch + i * 4) = v;
        }
    }
    if (m0 != n0) {
        int i = tid & 127;
        int jb = tid >> 7;          // 0..3
        #pragma unroll 4
        for (int jj = 0; jj < 32; jj++) {
            int j = jj * 4 + jb;
            Cb[(n0 + j) * SS + m0 + i] = stage[i * SPITCH + j];
        }
    }
}

// =============================================================================
// HMMA GEMM: C[m,n] = sum_k A[k*512+m] * B[n*512+k], K=512, warp-specialized.
// =============================================================================
template <bool EPI>
__global__ void __launch_bounds__(512)
gemm_mma_kernel(const float* __restrict__ A, long sA,
                const float* __restrict__ B,
                float* __restrict__ C, long sC,
                const float* __restrict__ e_rm, const float* __restrict__ e_rn,
                const float* __restrict__ e_bm, const float* __restrict__ e_bn,
                float e_scale)
{
    int m0 = blockIdx.y * 128, n0 = blockIdx.x * 128;
    int b  = blockIdx.z;
    A += (long)b * sA;

    extern __shared__ char smem[];
    int tid = threadIdx.x;
    int wid = tid >> 5, lane = tid & 31;
    bool producer = (wid < 8);

    int isB  = (wid >> 2) & 1;
    int mloc = (wid & 3) * 32 + lane;
    int toff = isB ? OFF_BHI : OFF_AHI;
    const float* asrc = A + m0 + mloc;               // A[k][m0+mloc]
    const float* bsrc = B + (long)(n0 + mloc) * SS;  // B[n0+mloc][k]

    int cwid = wid - 8;
    int m_w = (cwid & 1) * 64;
    int n_w = (cwid >> 1) * 32;
    int g = lane >> 2, tg = lane & 3;

    float acc[4][4][4];
    #pragma unroll
    for (int mt = 0; mt < 4; mt++)
        #pragma unroll
        for (int nt = 0; nt < 4; nt++)
            #pragma unroll
            for (int r = 0; r < 4; r++) acc[mt][nt][r] = 0.f;

    const int NC = SS / 64;     // 8
    if (producer) {
        char* base = smem + toff;
        if (!isB) produce_strided(base, base + TBYTES, mloc, asrc);
        else      produce_contig (base, base + TBYTES, mloc, bsrc);
    }
    __syncthreads();

    for (int c = 0; c < NC; c++) {
        if (producer) {
            if (c + 1 < NC) {
                char* base = smem + ((c + 1) & 1) * SETBYTES + toff;
                if (!isB) produce_strided(base, base + TBYTES, mloc,
                                          asrc + (long)(c + 1) * 64 * SS);
                else      produce_contig (base, base + TBYTES, mloc,
                                          bsrc + (c + 1) * 64);
            }
        } else {
            consume_chunk(smem + (c & 1) * SETBYTES, m_w, n_w, g, tg, acc);
        }
        __syncthreads();
    }

    float* stage = (float*)smem;
    if (!producer) {
        #pragma unroll
        for (int mt = 0; mt < 4; mt++) {
            int r0 = m_w + mt * 16 + g;
            #pragma unroll
            for (int nt = 0; nt < 4; nt++) {
                int cc = n_w + nt * 8 + tg * 2;
                *(float2*)&stage[r0 * SPITCH + cc]       = make_float2(acc[mt][nt][0], acc[mt][nt][1]);
                *(float2*)&stage[(r0 + 8) * SPITCH + cc] = make_float2(acc[mt][nt][2], acc[mt][nt][3]);
            }
        }
    }
    __syncthreads();

    float* Cb = C + (long)b * sC;
    int row = tid >> 2, ch = (tid & 3) * 32;
    int m = m0 + row;
    float km = 0.f, bm = 0.f;
    if (EPI) { km = e_rm[b * SS + m]; bm = e_bm[m]; }
    #pragma unroll
    for (int i = 0; i < 8; i++) {
        float4 v = *(float4*)&stage[row * SPITCH + ch + i * 4];
        if (EPI) {
            int n = n0 + ch + i * 4;
            v.x += km * e_bn[n + 0] + bm * (e_rn[b * SS + n + 0] + e_scale * e_bn[n + 0]);
            v.y += km * e_bn[n + 1] + bm * (e_rn[b * SS + n + 1] + e_scale * e_bn[n + 1]);
            v.z += km * e_bn[n + 2] + bm * (e_rn[b * SS + n + 2] + e_scale * e_bn[n + 2]);
            v.w += km * e_bn[n + 3] + bm * (e_rn[b * SS + n + 3] + e_scale * e_bn[n + 3]);
        }
        *(float4*)(Cb + (long)m * SS + n0 + ch + i * 4) = v;
    }
}

// ---------------- column sums: s[b,c] = sum_i X[b,i,c] ----------------------
__global__ void colsum_part_kernel(const float* __restrict__ x) {
    int slab = blockIdx.x, b = blockIdx.y, c = threadIdx.x;
    const float* p = x + ((long)b * INCD + slab * 128) * SS + c;
    float acc = 0.f;
    #pragma unroll 8
    for (int i = 0; i < 128; i++) acc += p[i * SS];
    g_part[(slab * BB + b) * SS + c] = acc;
}
__global__ void colsum_reduce_kernel() {
    int b = blockIdx.x, c = threadIdx.x;
    float acc = 0.f;
    #pragma unroll
    for (int slab = 0; slab < 16; slab++) acc += g_part[(slab * BB + b) * SS + c];
    g_s[b * SS + c] = acc;
}
__global__ void kkq_kernel(const float* __restrict__ Wk, const float* __restrict__ Wq) {
    int b = blockIdx.x, which = blockIdx.y, row = threadIdx.x;
    __shared__ float ss[SS];
    ss[row] = g_s[b * SS + row];
    __syncthreads();
    const float* wr = (which ? Wq : Wk) + row * SS;
    float acc = 0.f;
    #pragma unroll 8
    for (int c = 0; c < SS; c++) acc += wr[c] * ss[c];
    if (which) g_kq[b * SS + row] = acc;
    else       g_kk[b * SS + row] = acc;
}

// ---------------- fused softmax + partial w ----------------------------------
__global__ void softmax_w_kernel(const float* __restrict__ Wout) {
    int chunk = blockIdx.x, b = blockIdx.y, tid = threadIdx.x;
    __shared__ float red[256];
    __shared__ float wpart[SS];
    wpart[tid] = 0.f; wpart[tid + 256] = 0.f;
    __syncthreads();
    const float* Eb = g_bufA + (long)b * SS * SS;
    for (int r = 0; r < 16; r++) {
        int s = chunk * 16 + r;
        const float* row = Eb + s * SS;
        float e0 = row[tid], e1 = row[tid + 256];
        red[tid] = fmaxf(e0, e1);
        __syncthreads();
        for (int st = 128; st > 0; st >>= 1) {
            if (tid < st) red[tid] = fmaxf(red[tid], red[tid + st]);
            __syncthreads();
        }
        float mx = red[0];
        __syncthreads();
        e0 = expf(e0 - mx); e1 = expf(e1 - mx);
        red[tid] = e0 + e1;
        __syncthreads();
        for (int st = 128; st > 0; st >>= 1) {
            if (tid < st) red[tid] += red[tid + st];
            __syncthreads();
        }
        float scale = Wout[s] / red[0];
        wpart[tid]       += e0 * scale;
        wpart[tid + 256] += e1 * scale;
        __syncthreads();
    }
    float* dst = g_part + (chunk * BB + b) * SS;
    dst[tid] = wpart[tid];
    dst[tid + 256] = wpart[tid + 256];
}
__global__ void w_reduce_kernel() {
    int b = blockIdx.x, t = threadIdx.x;
    float acc = 0.f;
    #pragma unroll
    for (int chunk = 0; chunk < 32; chunk++) acc += g_part[(chunk * BB + b) * SS + t];
    g_w[b * SS + t] = acc;
}
__global__ void u_kernel(const float* __restrict__ Wv, const float* __restrict__ bv,
                         const float* __restrict__ bout) {
    int b = blockIdx.x, c = threadIdx.x;
    __shared__ float ws[SS];
    __shared__ float red[SS];
    ws[c] = g_w[b * SS + c];
    __syncthreads();
    float acc = 0.f;
    #pragma unroll 8
    for (int t = 0; t < SS; t++) acc += ws[t] * Wv[t * SS + c];
    g_u[b * SS + c] = acc;
    red[c] = ws[c] * bv[c];
    __syncthreads();
    for (int s = 256; s > 0; s >>= 1) {
        if (c < s) red[c] += red[c + s];
        __syncthreads();
    }
    if (c == 0) g_cc[b] = red[0] + bout[0];
}
__global__ void out_kernel(const float* __restrict__ x, float* __restrict__ out) {
    int b = blockIdx.y, i0 = blockIdx.x * 8, tid = threadIdx.x;
    __shared__ float us[SS];
    us[tid] = g_u[b * SS + tid];
    us[tid + 256] = g_u[b * SS + tid + 256];
    __syncthreads();
    int warp = tid >> 5, lane = tid & 31;
    int i = i0 + warp;
    const float* xr = x + ((long)b * INCD + i) * SS;
    float acc = 0.f;
    #pragma unroll
    for (int s = lane; s < SS; s += 32) acc += xr[s] * us[s];
    #pragma unroll
    for (int o = 16; o > 0; o >>= 1) acc += __shfl_xor_sync(0xffffffffu, acc, o);
    if (lane == 0) out[(long)b * INCD + i] = acc + g_cc[b];
}

// ---------------- launch -----------------------------------------------------
extern "C" void kernel_launch(void* const* d_in, const int* in_sizes, int n_in,
                              void* d_out, int out_size) {
    const float* x    = (const float*)d_in[0];
    const float* Wq   = (const float*)d_in[1];
    const float* bq   = (const float*)d_in[2];
    const float* Wk   = (const float*)d_in[3];
    const float* bk   = (const float*)d_in[4];
    const float* Wv   = (const float*)d_in[5];
    const float* bv   = (const float*)d_in[6];
    const float* Wout = (const float*)d_in[7];
    const float* bout = (const float*)d_in[8];
    float* out = (float*)d_out;

    void *pA, *pB, *pkk, *pkq;
    cudaGetSymbolAddress(&pA,  g_bufA);
    cudaGetSymbolAddress(&pB,  g_bufB);
    cudaGetSymbolAddress(&pkk, g_kk);
    cudaGetSymbolAddress(&pkq, g_kq);
    float* bufA = (float*)pA;
    float* bufB = (float*)pB;
    float* kk   = (float*)pkk;
    float* kq   = (float*)pkq;

    const long sBatch = (long)SS * SS;

    cudaFuncSetAttribute(gram_mma_kernel,
                         cudaFuncAttributeMaxDynamicSharedMemorySize, MMA_SMEM);
    cudaFuncSetAttribute(gemm_mma_kernel<false>,
                         cudaFuncAttributeMaxDynamicSharedMemorySize, MMA_SMEM);
    cudaFuncSetAttribute(gemm_mma_kernel<true>,
                         cudaFuncAttributeMaxDynamicSharedMemorySize, MMA_SMEM);

    // 1) column sums -> s, then kk = Wk s, kq = Wq s
    colsum_part_kernel<<<dim3(16, BB), SS>>>(x);
    colsum_reduce_kernel<<<BB, SS>>>();
    kkq_kernel<<<dim3(BB, 2), SS>>>(Wk, Wq);

    // 2) G = X^T X via warp-specialized HMMA -> bufA
    gram_mma_kernel<<<dim3(10, BB), 512, MMA_SMEM>>>(x, bufA);

    // 3) M2 = G Wk^T -> bufB
    gemm_mma_kernel<false><<<dim3(4, 4, BB), 512, MMA_SMEM>>>(
        bufA, sBatch, Wk, bufB, sBatch,
        nullptr, nullptr, nullptr, nullptr, 0.f);

    // 4) E = M2^T Wq^T (= Wk G Wq^T) + rank-1 -> bufA
    gemm_mma_kernel<true><<<dim3(4, 4, BB), 512, MMA_SMEM>>>(
        bufB, sBatch, Wq, bufA, sBatch,
        kk, kq, bk, bq, (float)INCD);

    // 5) fused softmax + w partials, then reduce
    softmax_w_kernel<<<dim3(32, BB), 256>>>(Wout);
    w_reduce_kernel<<<BB, SS>>>();

    // 6) u = Wv^T w, cc = w.bv + bout
    u_kernel<<<BB, SS>>>(Wv, bv, bout);

    // 7) out = X u + cc
    out_kernel<<<dim3(INCD / 8, BB), 256>>>(x, out);
}